// round 15
// baseline (speedup 1.0000x reference)
#include <cuda_runtime.h>
#include <cuda_bf16.h>
#include <math.h>
#include <stdint.h>

#define B_ROWS 4096
#define N_ROWS 8192
#define DIM    1024
#define TEMP   0.07f
#define INV_TEMP (1.0f/0.07f)

#define Q_SCALE    512.0f
#define ACC_SCALE  (1.0f/(512.0f*512.0f))

#define TS     128                     // tile size (M=N=128)
#define NT     (N_ROWS / TS)           // 64 tile-blocks
#define NPAIRS (NT * (NT + 1) / 2)     // 2080 upper-tri tiles
#define BK     128                     // K chunk (int8 elems = bytes)
#define NCHUNK (DIM / BK)              // 8
#define STRIDEB 144                    // smem row stride in bytes (proven config)
#define TILE_SM (128 * STRIDEB)        // 18432 B per operand tile
#define STAGE_BYTES (2 * TILE_SM)      // A+B per stage = 36864
#define SMEM_BYTES (2 * STAGE_BYTES)   // 73728 B double-buffered

// accumulators: [0]=cls_sum, [1]=kl_sum, [2]=cos_sum
__device__ float g_acc[4];
__device__ float g_lsum[N_ROWS];
__device__ float g_pos[B_ROWS];
__device__ unsigned int g_done;          // last-CTA counter for fused finalize
__device__ uint8_t g_q8[N_ROWS * DIM];   // s8 of (normalized * 512)

// ---------------------------------------------------------------------------
__device__ __forceinline__ uint32_t smem_to_u32(const void* p) {
    uint32_t a;
    asm("{ .reg .u64 t; cvta.to.shared.u64 t, %1; cvt.u32.u64 %0, t; }" : "=r"(a) : "l"(p));
    return a;
}
__device__ __forceinline__ void cp_async16(uint32_t dst, const void* src) {
    asm volatile("cp.async.cg.shared.global [%0], [%1], 16;"
                 :: "r"(dst), "l"(__cvta_generic_to_global(src)) : "memory");
}
__device__ __forceinline__ void ldsm_x4(uint32_t* r, uint32_t addr) {
    asm volatile("ldmatrix.sync.aligned.m8n8.x4.shared.b16 {%0,%1,%2,%3}, [%4];"
                 : "=r"(r[0]), "=r"(r[1]), "=r"(r[2]), "=r"(r[3]) : "r"(addr));
}
// int8 IMMA, k=32, s32 accumulate
__device__ __forceinline__ void mma16832s8(int* d, const uint32_t* a, uint32_t b0, uint32_t b1) {
    asm volatile("mma.sync.aligned.m16n8k32.row.col.s32.s8.s8.s32 "
                 "{%0,%1,%2,%3}, {%4,%5,%6,%7}, {%8,%9}, {%0,%1,%2,%3};"
                 : "+r"(d[0]), "+r"(d[1]), "+r"(d[2]), "+r"(d[3])
                 : "r"(a[0]), "r"(a[1]), "r"(a[2]), "r"(a[3]), "r"(b0), "r"(b1));
}

// ---------------------------------------------------------------------------
// Warp-per-row prep, two-pass, register-capped (<=64 regs -> 4 CTAs/SM).
__global__ void __launch_bounds__(256, 4) prep_kernel(
        const float* __restrict__ sfeat, const float* __restrict__ slog,
        const float* __restrict__ tfeat, const float* __restrict__ tlog,
        const int* __restrict__ labels,  const float* __restrict__ sfaug) {
    int t = threadIdx.x, lane = t & 31, wib = t >> 5;
    int row = blockIdx.x * 8 + wib;

    if (blockIdx.x < 32) g_lsum[blockIdx.x * 256 + t] = 0.0f;
    if (blockIdx.x == 0 && t < 4) g_acc[t] = 0.0f;
    if (blockIdx.x == 0 && t == 32) g_done = 0u;

    const float4* s4 = (const float4*)(sfeat + (size_t)row * DIM);
    const float4* t4 = (const float4*)(tfeat + (size_t)row * DIM);
    const float4* a4 = (const float4*)(sfaug + (size_t)row * DIM);

    float ss = 0.0f, st = 0.0f, sa = 0.0f, dst_ = 0.0f, dsa = 0.0f;
    #pragma unroll
    for (int i = 0; i < 8; i++) {
        float4 s = s4[lane + 32 * i];
        float4 tv = t4[lane + 32 * i];
        float4 a = a4[lane + 32 * i];
        ss   += s.x * s.x + s.y * s.y + s.z * s.z + s.w * s.w;
        st   += tv.x * tv.x + tv.y * tv.y + tv.z * tv.z + tv.w * tv.w;
        sa   += a.x * a.x + a.y * a.y + a.z * a.z + a.w * a.w;
        dst_ += s.x * tv.x + s.y * tv.y + s.z * tv.z + s.w * tv.w;
        dsa  += s.x * a.x + s.y * a.y + s.z * a.z + s.w * a.w;
    }
    #pragma unroll
    for (int o = 16; o > 0; o >>= 1) {
        ss   += __shfl_xor_sync(0xffffffffu, ss, o);
        st   += __shfl_xor_sync(0xffffffffu, st, o);
        sa   += __shfl_xor_sync(0xffffffffu, sa, o);
        dst_ += __shfl_xor_sync(0xffffffffu, dst_, o);
        dsa  += __shfl_xor_sync(0xffffffffu, dsa, o);
    }
    float ns = fmaxf(sqrtf(ss), 1e-12f);
    float na = fmaxf(sqrtf(sa), 1e-12f);
    float inv_s = Q_SCALE / ns;
    float inv_a = Q_SCALE / na;

    uint32_t* qs = (uint32_t*)(g_q8 + (size_t)row * DIM);
    uint32_t* qa = (uint32_t*)(g_q8 + (size_t)(row + B_ROWS) * DIM);
    #pragma unroll
    for (int i = 0; i < 8; i++) {
        float4 s = s4[lane + 32 * i];
        float4 a = a4[lane + 32 * i];
        int q0 = max(-127, min(127, __float2int_rn(s.x * inv_s)));
        int q1 = max(-127, min(127, __float2int_rn(s.y * inv_s)));
        int q2 = max(-127, min(127, __float2int_rn(s.z * inv_s)));
        int q3 = max(-127, min(127, __float2int_rn(s.w * inv_s)));
        qs[lane + 32 * i] = (uint32_t)(q0 & 0xff) | ((uint32_t)(q1 & 0xff) << 8)
                          | ((uint32_t)(q2 & 0xff) << 16) | ((uint32_t)(q3 & 0xff) << 24);
        q0 = max(-127, min(127, __float2int_rn(a.x * inv_a)));
        q1 = max(-127, min(127, __float2int_rn(a.y * inv_a)));
        q2 = max(-127, min(127, __float2int_rn(a.z * inv_a)));
        q3 = max(-127, min(127, __float2int_rn(a.w * inv_a)));
        qa[lane + 32 * i] = (uint32_t)(q0 & 0xff) | ((uint32_t)(q1 & 0xff) << 8)
                          | ((uint32_t)(q2 & 0xff) << 16) | ((uint32_t)(q3 & 0xff) << 24);
    }

    float cls = 0.0f, kl = 0.0f, cosv = 0.0f;
    if (lane == 0) {
        cosv = dst_ / (ns * fmaxf(sqrtf(st), 1e-12f));
        g_pos[row] = dsa / (ns * na);

        float s0 = slog[2 * row], s1 = slog[2 * row + 1];
        float t0 = tlog[2 * row], t1 = tlog[2 * row + 1];
        float mx = fmaxf(s0, s1);
        float lse = mx + logf(expf(s0 - mx) + expf(s1 - mx));
        int lab = labels[row];
        cls = -((lab == 0 ? s0 : s1) - lse);
        float a0 = t0 * INV_TEMP, a1 = t1 * INV_TEMP;
        float b0 = s0 * INV_TEMP, b1 = s1 * INV_TEMP;
        float am = fmaxf(a0, a1);
        float alse = am + logf(expf(a0 - am) + expf(a1 - am));
        float bm = fmaxf(b0, b1);
        float blse = bm + logf(expf(b0 - bm) + expf(b1 - bm));
        float tlp0 = a0 - alse, tlp1 = a1 - alse;
        float slp0 = b0 - blse, slp1 = b1 - blse;
        kl = expf(tlp0) * (tlp0 - slp0) + expf(tlp1) * (tlp1 - slp1);
    }
    __shared__ float sc[8], sk[8], sco[8];
    if (lane == 0) { sc[wib] = cls; sk[wib] = kl; sco[wib] = cosv; }
    __syncthreads();
    if (t == 0) {
        float c = 0, k = 0, co = 0;
        #pragma unroll
        for (int i = 0; i < 8; i++) { c += sc[i]; k += sk[i]; co += sco[i]; }
        atomicAdd(&g_acc[0], c);
        atomicAdd(&g_acc[1], k);
        atomicAdd(&g_acc[2], co);
    }
}

// ---------------------------------------------------------------------------
// SimCLR via int8 IMMA m16n8k32: one CTA per upper-tri 128x128 tile.
// 8 warps as 2(M) x 4(N); warp tile 64x32; double-buffered, ONE barrier per
// chunk (wait_group 0 -> barrier -> prefetch c+1 -> compute c).
// Last CTA to finish performs the final reduction and writes the 5 outputs.
__global__ void __launch_bounds__(256, 2) simclr_mma_kernel(
        float* __restrict__ out, int out_size) {
    extern __shared__ char smem[];
    __shared__ float row_acc[128];
    __shared__ float col_acc[128];
    __shared__ int s_last;
    uint32_t sm = smem_to_u32(smem);
    int t = threadIdx.x, wid = t >> 5, lane = t & 31;

    // decode upper-triangular tile (rb, cb), cb >= rb
    int id = blockIdx.x;
    #define CUM(r) (((r) * (2 * NT + 1 - (r))) >> 1)
    int rb = (int)((2 * NT + 1 - sqrtf((float)(2 * NT + 1) * (2 * NT + 1) - 8.0f * id)) * 0.5f);
    if (rb < 0) rb = 0;
    while (rb > 0 && CUM(rb) > id) rb--;
    while (CUM(rb + 1) <= id) rb++;
    int cb = rb + (id - CUM(rb));
    #undef CUM
    int row0 = rb * TS, col0 = cb * TS;
    bool diag = (rb == cb);

    if (t < 128) { row_acc[t] = 0.0f; col_acc[t] = 0.0f; }

    int warp_m = wid >> 2, warp_n = wid & 3;

    int acc[4][4][4];
    #pragma unroll
    for (int i = 0; i < 4; i++)
        #pragma unroll
        for (int j = 0; j < 4; j++)
            #pragma unroll
            for (int v = 0; v < 4; v++) acc[i][j][v] = 0;

    const uint8_t* gA = g_q8 + (size_t)row0 * DIM;
    const uint8_t* gB = g_q8 + (size_t)col0 * DIM;
    int r_ld = t >> 3, c16 = t & 7;    // 4 rows per thread (r_ld+32i), one 16B unit

    // prologue: issue chunk 0
    {
        uint32_t dA = sm;
        uint32_t dB = dA + TILE_SM;
        #pragma unroll
        for (int i = 0; i < 4; i++) {
            int r = r_ld + 32 * i;
            cp_async16(dA + r * STRIDEB + c16 * 16, gA + (size_t)r * DIM + c16 * 16);
            cp_async16(dB + r * STRIDEB + c16 * 16, gB + (size_t)r * DIM + c16 * 16);
        }
        asm volatile("cp.async.commit_group;" ::: "memory");
    }

    // per-lane fragment addresses (byte offsets within a stage)
    uint32_t aRow = warp_m * 64 + (lane & 15);
    uint32_t aColB = (lane >> 4) * 16;
    uint32_t bRow = warp_n * 32 + ((lane >> 4) << 3) + (lane & 7);
    uint32_t bColB = ((lane >> 3) & 1) * 16;
    uint32_t aFragOff = aRow * STRIDEB + aColB;
    uint32_t bFragOff = TILE_SM + bRow * STRIDEB + bColB;

    for (int c = 0; c < NCHUNK; c++) {
        int buf = c & 1;
        asm volatile("cp.async.wait_group 0;" ::: "memory");
        __syncthreads();

        // prefetch chunk c+1 into buf^1 (safe: its readers finished pre-barrier)
        if (c + 1 < NCHUNK) {
            int k0 = (c + 1) * BK;
            uint32_t dA = sm + (buf ^ 1) * STAGE_BYTES;
            uint32_t dB = dA + TILE_SM;
            #pragma unroll
            for (int i = 0; i < 4; i++) {
                int r = r_ld + 32 * i;
                cp_async16(dA + r * STRIDEB + c16 * 16, gA + (size_t)r * DIM + k0 + c16 * 16);
                cp_async16(dB + r * STRIDEB + c16 * 16, gB + (size_t)r * DIM + k0 + c16 * 16);
            }
            asm volatile("cp.async.commit_group;" ::: "memory");
        }

        uint32_t stage = sm + buf * STAGE_BYTES;
        #pragma unroll
        for (int ks = 0; ks < 4; ks++) {        // 4 k32 steps per 128B chunk
            uint32_t af[4][4], bf[2][4];
            #pragma unroll
            for (int mt = 0; mt < 4; mt++)
                ldsm_x4(af[mt], stage + aFragOff + mt * 16 * STRIDEB + ks * 32);
            #pragma unroll
            for (int pr = 0; pr < 2; pr++)
                ldsm_x4(bf[pr], stage + bFragOff + pr * 16 * STRIDEB + ks * 32);
            #pragma unroll
            for (int mt = 0; mt < 4; mt++)
                #pragma unroll
                for (int nt = 0; nt < 4; nt++)
                    mma16832s8(acc[mt][nt], af[mt], bf[nt >> 1][(nt & 1) * 2], bf[nt >> 1][(nt & 1) * 2 + 1]);
        }
    }

    // --- epilogue: exp + row/col sums in registers ---
    const float k1 = INV_TEMP * ACC_SCALE;
    int rq = lane >> 2, cq = lane & 3;
    int rbase = row0 + warp_m * 64;
    int cbase = col0 + warp_n * 32;
    float rs[4][2], cs[4][2];
    #pragma unroll
    for (int i = 0; i < 4; i++) { rs[i][0] = rs[i][1] = cs[i][0] = cs[i][1] = 0.0f; }

    #pragma unroll
    for (int mt = 0; mt < 4; mt++) {
        #pragma unroll
        for (int nt = 0; nt < 4; nt++) {
            float e0 = __expf(fmaf((float)acc[mt][nt][0], k1, -INV_TEMP));
            float e1 = __expf(fmaf((float)acc[mt][nt][1], k1, -INV_TEMP));
            float e2 = __expf(fmaf((float)acc[mt][nt][2], k1, -INV_TEMP));
            float e3 = __expf(fmaf((float)acc[mt][nt][3], k1, -INV_TEMP));
            if (diag) {
                int r0g = rbase + mt * 16 + rq, r1g = r0g + 8;
                int c0g = cbase + nt * 8 + cq * 2, c1g = c0g + 1;
                if (r0g == c0g) e0 = 0.0f;
                if (r0g == c1g) e1 = 0.0f;
                if (r1g == c0g) e2 = 0.0f;
                if (r1g == c1g) e3 = 0.0f;
            }
            rs[mt][0] += e0 + e1; rs[mt][1] += e2 + e3;
            cs[nt][0] += e0 + e2; cs[nt][1] += e1 + e3;
        }
    }
    #pragma unroll
    for (int mt = 0; mt < 4; mt++) {
        #pragma unroll
        for (int h = 0; h < 2; h++) {
            float v = rs[mt][h];
            v += __shfl_xor_sync(0xffffffffu, v, 1);
            v += __shfl_xor_sync(0xffffffffu, v, 2);
            if (cq == 0) atomicAdd(&row_acc[warp_m * 64 + mt * 16 + rq + h * 8], v);
        }
    }
    #pragma unroll
    for (int nt = 0; nt < 4; nt++) {
        #pragma unroll
        for (int s = 0; s < 2; s++) {
            float v = cs[nt][s];
            v += __shfl_xor_sync(0xffffffffu, v, 4);
            v += __shfl_xor_sync(0xffffffffu, v, 8);
            v += __shfl_xor_sync(0xffffffffu, v, 16);
            if (lane < 4) atomicAdd(&col_acc[warp_n * 32 + nt * 8 + lane * 2 + s], v);
        }
    }
    __syncthreads();
    if (t < 128) {
        atomicAdd(&g_lsum[row0 + t], row_acc[t]);
        if (!diag) atomicAdd(&g_lsum[col0 + t], col_acc[t]);
    }

    // --- fused finalize: last CTA reduces and writes outputs ---
    __syncthreads();
    if (t == 0) {
        __threadfence();
        unsigned int prev = atomicAdd(&g_done, 1u);
        s_last = (prev == NPAIRS - 1);
    }
    __syncthreads();
    if (s_last) {
        __threadfence();
        float s = 0.0f;
        #pragma unroll
        for (int i = t; i < N_ROWS; i += 256) {
            float lse = INV_TEMP + logf(g_lsum[i]);
            float pos = g_pos[i & (B_ROWS - 1)] * INV_TEMP;
            s += lse - pos;
        }
        #pragma unroll
        for (int o = 16; o > 0; o >>= 1) s += __shfl_down_sync(0xffffffffu, s, o);
        if ((t & 31) == 0) row_acc[t >> 5] = s;
        __syncthreads();
        if (t == 0) {
            float simclr_sum = 0.0f;
            #pragma unroll
            for (int i = 0; i < 8; i++) simclr_sum += row_acc[i];
            float cls     = g_acc[0] / (float)B_ROWS;
            float distill = g_acc[1] / (float)B_ROWS * (TEMP * TEMP);
            float feature = 1.0f - g_acc[2] / (float)B_ROWS;
            float simclr  = simclr_sum / (float)N_ROWS;
            float total = cls + distill + 0.5f * feature + 0.3f * simclr;
            float vals[5] = { total, cls, distill, feature, simclr };
            int n = out_size < 5 ? out_size : 5;
            for (int i = 0; i < n; i++) out[i] = vals[i];
        }
    }
}

// ---------------------------------------------------------------------------
extern "C" void kernel_launch(void* const* d_in, const int* in_sizes, int n_in,
                              void* d_out, int out_size) {
    const float* sfeat  = (const float*)d_in[0];
    const float* slog   = (const float*)d_in[1];
    const float* tfeat  = (const float*)d_in[2];
    const float* tlog   = (const float*)d_in[3];
    const int*   labels = (const int*)d_in[4];
    const float* sfaug  = (const float*)d_in[5];
    float* out = (float*)d_out;

    cudaFuncSetAttribute(simclr_mma_kernel,
                         cudaFuncAttributeMaxDynamicSharedMemorySize, SMEM_BYTES);

    prep_kernel<<<B_ROWS / 8, 256>>>(sfeat, slog, tfeat, tlog, labels, sfaug);
    simclr_mma_kernel<<<NPAIRS, 256, SMEM_BYTES>>>(out, out_size);
}

// round 16
// speedup vs baseline: 1.0453x; 1.0453x over previous
#include <cuda_runtime.h>
#include <cuda_bf16.h>
#include <math.h>
#include <stdint.h>

#define B_ROWS 4096
#define N_ROWS 8192
#define DIM    1024
#define TEMP   0.07f
#define INV_TEMP (1.0f/0.07f)

#define Q_SCALE    512.0f
#define ACC_SCALE  (1.0f/(512.0f*512.0f))

#define TS     128                     // tile size (M=N=128)
#define NT     (N_ROWS / TS)           // 64 tile-blocks
#define NPAIRS (NT * (NT + 1) / 2)     // 2080 upper-tri tiles
#define BK     128                     // K chunk (int8 elems = bytes)
#define NCHUNK (DIM / BK)              // 8
#define STRIDEB 144                    // smem row stride in bytes (proven config)
#define TILE_SM (128 * STRIDEB)        // 18432 B per operand tile
#define STAGE_BYTES (2 * TILE_SM)      // A+B per stage = 36864
#define SMEM_BYTES (2 * STAGE_BYTES)   // 73728 B double-buffered

// accumulators: [0]=cls_sum, [1]=kl_sum, [2]=cos_sum
__device__ float g_acc[4];
__device__ float g_lsum[N_ROWS];
__device__ float g_pos[B_ROWS];
__device__ uint8_t g_q8[N_ROWS * DIM];   // s8 of (normalized * 512)

// ---------------------------------------------------------------------------
__device__ __forceinline__ uint32_t smem_to_u32(const void* p) {
    uint32_t a;
    asm("{ .reg .u64 t; cvta.to.shared.u64 t, %1; cvt.u32.u64 %0, t; }" : "=r"(a) : "l"(p));
    return a;
}
__device__ __forceinline__ void cp_async16(uint32_t dst, const void* src) {
    asm volatile("cp.async.cg.shared.global [%0], [%1], 16;"
                 :: "r"(dst), "l"(__cvta_generic_to_global(src)) : "memory");
}
__device__ __forceinline__ void ldsm_x4(uint32_t* r, uint32_t addr) {
    asm volatile("ldmatrix.sync.aligned.m8n8.x4.shared.b16 {%0,%1,%2,%3}, [%4];"
                 : "=r"(r[0]), "=r"(r[1]), "=r"(r[2]), "=r"(r[3]) : "r"(addr));
}
// int8 IMMA, k=32, s32 accumulate
__device__ __forceinline__ void mma16832s8(int* d, const uint32_t* a, uint32_t b0, uint32_t b1) {
    asm volatile("mma.sync.aligned.m16n8k32.row.col.s32.s8.s8.s32 "
                 "{%0,%1,%2,%3}, {%4,%5,%6,%7}, {%8,%9}, {%0,%1,%2,%3};"
                 : "+r"(d[0]), "+r"(d[1]), "+r"(d[2]), "+r"(d[3])
                 : "r"(a[0]), "r"(a[1]), "r"(a[2]), "r"(a[3]), "r"(b0), "r"(b1));
}

// ---------------------------------------------------------------------------
// Warp-per-row prep, two-pass. 128-thread blocks (4 warps) for higher
// occupancy at 96 regs (5 CTAs/SM) and finer wave balance (1024 blocks).
__global__ void __launch_bounds__(128) prep_kernel(
        const float* __restrict__ sfeat, const float* __restrict__ slog,
        const float* __restrict__ tfeat, const float* __restrict__ tlog,
        const int* __restrict__ labels,  const float* __restrict__ sfaug) {
    int t = threadIdx.x, lane = t & 31, wib = t >> 5;
    int row = blockIdx.x * 4 + wib;

    if (blockIdx.x < 64) g_lsum[blockIdx.x * 128 + t] = 0.0f;
    if (blockIdx.x == 0 && t < 4) g_acc[t] = 0.0f;

    const float4* s4 = (const float4*)(sfeat + (size_t)row * DIM);
    const float4* t4 = (const float4*)(tfeat + (size_t)row * DIM);
    const float4* a4 = (const float4*)(sfaug + (size_t)row * DIM);

    float ss = 0.0f, st = 0.0f, sa = 0.0f, dst_ = 0.0f, dsa = 0.0f;
    #pragma unroll
    for (int i = 0; i < 8; i++) {
        float4 s = s4[lane + 32 * i];
        float4 tv = t4[lane + 32 * i];
        float4 a = a4[lane + 32 * i];
        ss   += s.x * s.x + s.y * s.y + s.z * s.z + s.w * s.w;
        st   += tv.x * tv.x + tv.y * tv.y + tv.z * tv.z + tv.w * tv.w;
        sa   += a.x * a.x + a.y * a.y + a.z * a.z + a.w * a.w;
        dst_ += s.x * tv.x + s.y * tv.y + s.z * tv.z + s.w * tv.w;
        dsa  += s.x * a.x + s.y * a.y + s.z * a.z + s.w * a.w;
    }
    #pragma unroll
    for (int o = 16; o > 0; o >>= 1) {
        ss   += __shfl_xor_sync(0xffffffffu, ss, o);
        st   += __shfl_xor_sync(0xffffffffu, st, o);
        sa   += __shfl_xor_sync(0xffffffffu, sa, o);
        dst_ += __shfl_xor_sync(0xffffffffu, dst_, o);
        dsa  += __shfl_xor_sync(0xffffffffu, dsa, o);
    }
    float ns = fmaxf(sqrtf(ss), 1e-12f);
    float na = fmaxf(sqrtf(sa), 1e-12f);
    float inv_s = Q_SCALE / ns;
    float inv_a = Q_SCALE / na;

    uint32_t* qs = (uint32_t*)(g_q8 + (size_t)row * DIM);
    uint32_t* qa = (uint32_t*)(g_q8 + (size_t)(row + B_ROWS) * DIM);
    #pragma unroll
    for (int i = 0; i < 8; i++) {
        float4 s = s4[lane + 32 * i];
        float4 a = a4[lane + 32 * i];
        int q0 = max(-127, min(127, __float2int_rn(s.x * inv_s)));
        int q1 = max(-127, min(127, __float2int_rn(s.y * inv_s)));
        int q2 = max(-127, min(127, __float2int_rn(s.z * inv_s)));
        int q3 = max(-127, min(127, __float2int_rn(s.w * inv_s)));
        qs[lane + 32 * i] = (uint32_t)(q0 & 0xff) | ((uint32_t)(q1 & 0xff) << 8)
                          | ((uint32_t)(q2 & 0xff) << 16) | ((uint32_t)(q3 & 0xff) << 24);
        q0 = max(-127, min(127, __float2int_rn(a.x * inv_a)));
        q1 = max(-127, min(127, __float2int_rn(a.y * inv_a)));
        q2 = max(-127, min(127, __float2int_rn(a.z * inv_a)));
        q3 = max(-127, min(127, __float2int_rn(a.w * inv_a)));
        qa[lane + 32 * i] = (uint32_t)(q0 & 0xff) | ((uint32_t)(q1 & 0xff) << 8)
                          | ((uint32_t)(q2 & 0xff) << 16) | ((uint32_t)(q3 & 0xff) << 24);
    }

    float cls = 0.0f, kl = 0.0f, cosv = 0.0f;
    if (lane == 0) {
        cosv = dst_ / (ns * fmaxf(sqrtf(st), 1e-12f));
        g_pos[row] = dsa / (ns * na);

        float s0 = slog[2 * row], s1 = slog[2 * row + 1];
        float t0 = tlog[2 * row], t1 = tlog[2 * row + 1];
        float mx = fmaxf(s0, s1);
        float lse = mx + logf(expf(s0 - mx) + expf(s1 - mx));
        int lab = labels[row];
        cls = -((lab == 0 ? s0 : s1) - lse);
        float a0 = t0 * INV_TEMP, a1 = t1 * INV_TEMP;
        float b0 = s0 * INV_TEMP, b1 = s1 * INV_TEMP;
        float am = fmaxf(a0, a1);
        float alse = am + logf(expf(a0 - am) + expf(a1 - am));
        float bm = fmaxf(b0, b1);
        float blse = bm + logf(expf(b0 - bm) + expf(b1 - bm));
        float tlp0 = a0 - alse, tlp1 = a1 - alse;
        float slp0 = b0 - blse, slp1 = b1 - blse;
        kl = expf(tlp0) * (tlp0 - slp0) + expf(tlp1) * (tlp1 - slp1);
    }
    __shared__ float sc[4], sk[4], sco[4];
    if (lane == 0) { sc[wib] = cls; sk[wib] = kl; sco[wib] = cosv; }
    __syncthreads();
    if (t == 0) {
        float c = 0, k = 0, co = 0;
        #pragma unroll
        for (int i = 0; i < 4; i++) { c += sc[i]; k += sk[i]; co += sco[i]; }
        atomicAdd(&g_acc[0], c);
        atomicAdd(&g_acc[1], k);
        atomicAdd(&g_acc[2], co);
    }
}

// ---------------------------------------------------------------------------
// SimCLR via int8 IMMA m16n8k32: one CTA per upper-tri 128x128 tile.
// 8 warps as 2(M) x 4(N); warp tile 64x32; double-buffered, ONE barrier per
// chunk (wait_group 0 -> barrier -> prefetch c+1 -> compute c).  [R14 champion]
__global__ void __launch_bounds__(256, 2) simclr_mma_kernel() {
    extern __shared__ char smem[];
    __shared__ float row_acc[128];
    __shared__ float col_acc[128];
    uint32_t sm = smem_to_u32(smem);
    int t = threadIdx.x, wid = t >> 5, lane = t & 31;

    // decode upper-triangular tile (rb, cb), cb >= rb
    int id = blockIdx.x;
    #define CUM(r) (((r) * (2 * NT + 1 - (r))) >> 1)
    int rb = (int)((2 * NT + 1 - sqrtf((float)(2 * NT + 1) * (2 * NT + 1) - 8.0f * id)) * 0.5f);
    if (rb < 0) rb = 0;
    while (rb > 0 && CUM(rb) > id) rb--;
    while (CUM(rb + 1) <= id) rb++;
    int cb = rb + (id - CUM(rb));
    #undef CUM
    int row0 = rb * TS, col0 = cb * TS;
    bool diag = (rb == cb);

    if (t < 128) { row_acc[t] = 0.0f; col_acc[t] = 0.0f; }

    int warp_m = wid >> 2, warp_n = wid & 3;

    int acc[4][4][4];
    #pragma unroll
    for (int i = 0; i < 4; i++)
        #pragma unroll
        for (int j = 0; j < 4; j++)
            #pragma unroll
            for (int v = 0; v < 4; v++) acc[i][j][v] = 0;

    const uint8_t* gA = g_q8 + (size_t)row0 * DIM;
    const uint8_t* gB = g_q8 + (size_t)col0 * DIM;
    int r_ld = t >> 3, c16 = t & 7;    // 4 rows per thread (r_ld+32i), one 16B unit

    // prologue: issue chunk 0
    {
        uint32_t dA = sm;
        uint32_t dB = dA + TILE_SM;
        #pragma unroll
        for (int i = 0; i < 4; i++) {
            int r = r_ld + 32 * i;
            cp_async16(dA + r * STRIDEB + c16 * 16, gA + (size_t)r * DIM + c16 * 16);
            cp_async16(dB + r * STRIDEB + c16 * 16, gB + (size_t)r * DIM + c16 * 16);
        }
        asm volatile("cp.async.commit_group;" ::: "memory");
    }

    // per-lane fragment addresses (byte offsets within a stage)
    uint32_t aRow = warp_m * 64 + (lane & 15);
    uint32_t aColB = (lane >> 4) * 16;
    uint32_t bRow = warp_n * 32 + ((lane >> 4) << 3) + (lane & 7);
    uint32_t bColB = ((lane >> 3) & 1) * 16;
    uint32_t aFragOff = aRow * STRIDEB + aColB;
    uint32_t bFragOff = TILE_SM + bRow * STRIDEB + bColB;

    for (int c = 0; c < NCHUNK; c++) {
        int buf = c & 1;
        asm volatile("cp.async.wait_group 0;" ::: "memory");
        __syncthreads();

        // prefetch chunk c+1 into buf^1 (safe: its readers finished pre-barrier)
        if (c + 1 < NCHUNK) {
            int k0 = (c + 1) * BK;
            uint32_t dA = sm + (buf ^ 1) * STAGE_BYTES;
            uint32_t dB = dA + TILE_SM;
            #pragma unroll
            for (int i = 0; i < 4; i++) {
                int r = r_ld + 32 * i;
                cp_async16(dA + r * STRIDEB + c16 * 16, gA + (size_t)r * DIM + k0 + c16 * 16);
                cp_async16(dB + r * STRIDEB + c16 * 16, gB + (size_t)r * DIM + k0 + c16 * 16);
            }
            asm volatile("cp.async.commit_group;" ::: "memory");
        }

        uint32_t stage = sm + buf * STAGE_BYTES;
        #pragma unroll
        for (int ks = 0; ks < 4; ks++) {        // 4 k32 steps per 128B chunk
            uint32_t af[4][4], bf[2][4];
            #pragma unroll
            for (int mt = 0; mt < 4; mt++)
                ldsm_x4(af[mt], stage + aFragOff + mt * 16 * STRIDEB + ks * 32);
            #pragma unroll
            for (int pr = 0; pr < 2; pr++)
                ldsm_x4(bf[pr], stage + bFragOff + pr * 16 * STRIDEB + ks * 32);
            #pragma unroll
            for (int mt = 0; mt < 4; mt++)
                #pragma unroll
                for (int nt = 0; nt < 4; nt++)
                    mma16832s8(acc[mt][nt], af[mt], bf[nt >> 1][(nt & 1) * 2], bf[nt >> 1][(nt & 1) * 2 + 1]);
        }
    }

    // --- epilogue: exp + row/col sums in registers ---
    const float k1 = INV_TEMP * ACC_SCALE;
    int rq = lane >> 2, cq = lane & 3;
    int rbase = row0 + warp_m * 64;
    int cbase = col0 + warp_n * 32;
    float rs[4][2], cs[4][2];
    #pragma unroll
    for (int i = 0; i < 4; i++) { rs[i][0] = rs[i][1] = cs[i][0] = cs[i][1] = 0.0f; }

    #pragma unroll
    for (int mt = 0; mt < 4; mt++) {
        #pragma unroll
        for (int nt = 0; nt < 4; nt++) {
            float e0 = __expf(fmaf((float)acc[mt][nt][0], k1, -INV_TEMP));
            float e1 = __expf(fmaf((float)acc[mt][nt][1], k1, -INV_TEMP));
            float e2 = __expf(fmaf((float)acc[mt][nt][2], k1, -INV_TEMP));
            float e3 = __expf(fmaf((float)acc[mt][nt][3], k1, -INV_TEMP));
            if (diag) {
                int r0g = rbase + mt * 16 + rq, r1g = r0g + 8;
                int c0g = cbase + nt * 8 + cq * 2, c1g = c0g + 1;
                if (r0g == c0g) e0 = 0.0f;
                if (r0g == c1g) e1 = 0.0f;
                if (r1g == c0g) e2 = 0.0f;
                if (r1g == c1g) e3 = 0.0f;
            }
            rs[mt][0] += e0 + e1; rs[mt][1] += e2 + e3;
            cs[nt][0] += e0 + e2; cs[nt][1] += e1 + e3;
        }
    }
    #pragma unroll
    for (int mt = 0; mt < 4; mt++) {
        #pragma unroll
        for (int h = 0; h < 2; h++) {
            float v = rs[mt][h];
            v += __shfl_xor_sync(0xffffffffu, v, 1);
            v += __shfl_xor_sync(0xffffffffu, v, 2);
            if (cq == 0) atomicAdd(&row_acc[warp_m * 64 + mt * 16 + rq + h * 8], v);
        }
    }
    #pragma unroll
    for (int nt = 0; nt < 4; nt++) {
        #pragma unroll
        for (int s = 0; s < 2; s++) {
            float v = cs[nt][s];
            v += __shfl_xor_sync(0xffffffffu, v, 4);
            v += __shfl_xor_sync(0xffffffffu, v, 8);
            v += __shfl_xor_sync(0xffffffffu, v, 16);
            if (lane < 4) atomicAdd(&col_acc[warp_n * 32 + nt * 8 + lane * 2 + s], v);
        }
    }
    __syncthreads();
    if (t < 128) {
        atomicAdd(&g_lsum[row0 + t], row_acc[t]);
        if (!diag) atomicAdd(&g_lsum[col0 + t], col_acc[t]);
    }
}

// ---------------------------------------------------------------------------
__global__ void final_kernel(float* __restrict__ out, int out_size) {
    int t = threadIdx.x;
    float s = 0.0f;
    #pragma unroll
    for (int i = t; i < N_ROWS; i += 1024) {
        float lse = INV_TEMP + __logf(g_lsum[i]);
        float pos = g_pos[i & (B_ROWS - 1)] * INV_TEMP;
        s += lse - pos;
    }
    #pragma unroll
    for (int o = 16; o > 0; o >>= 1) s += __shfl_down_sync(0xffffffffu, s, o);
    __shared__ float wsum[32];
    if ((t & 31) == 0) wsum[t >> 5] = s;
    __syncthreads();
    if (t == 0) {
        float simclr_sum = 0.0f;
        #pragma unroll
        for (int i = 0; i < 32; i++) simclr_sum += wsum[i];
        float cls     = g_acc[0] / (float)B_ROWS;
        float distill = g_acc[1] / (float)B_ROWS * (TEMP * TEMP);
        float feature = 1.0f - g_acc[2] / (float)B_ROWS;
        float simclr  = simclr_sum / (float)N_ROWS;
        float total = cls + distill + 0.5f * feature + 0.3f * simclr;
        float vals[5] = { total, cls, distill, feature, simclr };
        int n = out_size < 5 ? out_size : 5;
        for (int i = 0; i < n; i++) out[i] = vals[i];
    }
}

// ---------------------------------------------------------------------------
extern "C" void kernel_launch(void* const* d_in, const int* in_sizes, int n_in,
                              void* d_out, int out_size) {
    const float* sfeat  = (const float*)d_in[0];
    const float* slog   = (const float*)d_in[1];
    const float* tfeat  = (const float*)d_in[2];
    const float* tlog   = (const float*)d_in[3];
    const int*   labels = (const int*)d_in[4];
    const float* sfaug  = (const float*)d_in[5];
    float* out = (float*)d_out;

    cudaFuncSetAttribute(simclr_mma_kernel,
                         cudaFuncAttributeMaxDynamicSharedMemorySize, SMEM_BYTES);

    prep_kernel<<<B_ROWS / 4, 128>>>(sfeat, slog, tfeat, tlog, labels, sfaug);
    simclr_mma_kernel<<<NPAIRS, 256, SMEM_BYTES>>>();
    final_kernel<<<1, 1024>>>(out, out_size);
}